// round 4
// baseline (speedup 1.0000x reference)
#include <cuda_runtime.h>
#include <cstdint>

// ===========================================================================
// reinforce_cons_loss:
//   K1 Threefry-2x32 Gumbel-max sampling. Rotates implemented as IMAD.WIDE
//      (fma pipe) + fused LOP3 to unload the saturated ALU pipe.
//   K2 5x5 fg-neighbor counts + per-(task,class) argmax seed (sliding window)
//   K3 per-(task,class) 8-connectivity flood fill (bitset row closure)
//      + component log-prob sum + last-CTA final loss reduction
// ===========================================================================

#define NIMG   4
#define NSAMP  10
#define HH     512
#define WW     512
#define NTASK  (NIMG*NSAMP)            // 40 image-samples
#define NPIX   (HH*WW)                 // 262144 = 1<<18
#define TOTPIX ((unsigned)NTASK*NPIX)  // 10485760

__device__ uint8_t            g_cls[(size_t)NTASK * NPIX];
__device__ unsigned long long g_seed[NTASK * 3];
__device__ double             g_partial[NTASK * 3];
__device__ int                g_done;

// Rotation multipliers 2^R for R = {13,15,26,6, 17,29,16,24}. Kept in a
// MUTABLE device global so ptxas cannot constant-fold the wide multiply back
// into shift pairs — guarantees IMAD.WIDE (fma pipe) with register operand.
__device__ __align__(16) uint32_t g_rmul[8] = {
    1u << 13, 1u << 15, 1u << 26, 1u << 6,
    1u << 17, 1u << 29, 1u << 16, 1u << 24
};

// ---------------------------------------------------------------------------
// Threefry-2x32, 20 rounds, key (0,42), counter (0, idx); out = x0 ^ x1
// (jax_threefry_partitionable — verified rounds 1-3, rel_err 6e-8)
// rotl(x,R) == lo|hi of the 64-bit product x * 2^R  (IMAD.WIDE, fma pipe);
// (lo|hi)^x0 fuses to one LOP3.
// ---------------------------------------------------------------------------
#define TFR(x0,x1,m) { x0 += x1;                                           \
    uint64_t _p = (uint64_t)(x1) * (uint64_t)(m);                          \
    x1 = (((uint32_t)_p) | ((uint32_t)(_p >> 32))) ^ x0; }

__device__ __forceinline__ uint32_t gumbel_bits(
        uint32_t idx,
        uint32_t m0, uint32_t m1, uint32_t m2, uint32_t m3,
        uint32_t m4, uint32_t m5, uint32_t m6, uint32_t m7) {
    const uint32_t k0 = 0u, k1 = 42u;
    const uint32_t k2 = k0 ^ k1 ^ 0x1BD11BDAu;
    uint32_t x0 = k0, x1 = idx + k1;
    TFR(x0,x1,m0) TFR(x0,x1,m1) TFR(x0,x1,m2) TFR(x0,x1,m3)
    x0 += k1; x1 += k2 + 1u;
    TFR(x0,x1,m4) TFR(x0,x1,m5) TFR(x0,x1,m6) TFR(x0,x1,m7)
    x0 += k2; x1 += k0 + 2u;
    TFR(x0,x1,m0) TFR(x0,x1,m1) TFR(x0,x1,m2) TFR(x0,x1,m3)
    x0 += k0; x1 += k1 + 3u;
    TFR(x0,x1,m4) TFR(x0,x1,m5) TFR(x0,x1,m6) TFR(x0,x1,m7)
    x0 += k1; x1 += k2 + 4u;
    TFR(x0,x1,m0) TFR(x0,x1,m1) TFR(x0,x1,m2) TFR(x0,x1,m3)
    x0 += k2; x1 += k0 + 5u;
    return x0 ^ x1;
}

// ---------------------------------------------------------------------------
// K1: gumbel-max, product form: argmax_c p_c / (-log2 u_c).
//   Fast path = MUFU __log2f; any comparison within a superset threshold of
//   the possible MUFU-induced flip region is redone with precise log2f ->
//   identical argmax to the verified precise path.
// ---------------------------------------------------------------------------
__global__ void __launch_bounds__(256) k_sample(const float* __restrict__ preds) {
    unsigned gid = blockIdx.x * 256u + threadIdx.x;
    if (blockIdx.x == 0) {
        if (threadIdx.x < NTASK * 3) g_seed[threadIdx.x] = 0ull;
        if (threadIdx.x == 0) g_done = 0;
    }
    if (gid >= TOTPIX) return;

    uint32_t m0 = g_rmul[0], m1 = g_rmul[1], m2 = g_rmul[2], m3 = g_rmul[3];
    uint32_t m4 = g_rmul[4], m5 = g_rmul[5], m6 = g_rmul[6], m7 = g_rmul[7];

    unsigned hw = gid & 0x3FFFFu;
    unsigned n  = (gid >> 18) & 3u;
    const float* pb = preds + ((size_t)n << 20) + hw;   // preds[n][c][h][w]
    unsigned base = gid << 2;

    float p0 = pb[0];
    float p1 = pb[(size_t)1 << 18];
    float p2 = pb[(size_t)2 << 18];
    float p3 = pb[(size_t)3 << 18];

    const float tiny = 1.17549435082228751e-38f;
    uint32_t b0 = gumbel_bits(base + 0, m0,m1,m2,m3,m4,m5,m6,m7);
    uint32_t b1 = gumbel_bits(base + 1, m0,m1,m2,m3,m4,m5,m6,m7);
    uint32_t b2 = gumbel_bits(base + 2, m0,m1,m2,m3,m4,m5,m6,m7);
    uint32_t b3 = gumbel_bits(base + 3, m0,m1,m2,m3,m4,m5,m6,m7);
    float u0 = fmaxf(__uint_as_float((b0 >> 9) | 0x3f800000u) - 1.0f, tiny);
    float u1 = fmaxf(__uint_as_float((b1 >> 9) | 0x3f800000u) - 1.0f, tiny);
    float u2 = fmaxf(__uint_as_float((b2 >> 9) | 0x3f800000u) - 1.0f, tiny);
    float u3 = fmaxf(__uint_as_float((b3 >> 9) | 0x3f800000u) - 1.0f, tiny);

    float w0 = -__log2f(u0);
    float w1 = -__log2f(u1);
    float w2 = -__log2f(u2);
    float w3 = -__log2f(u3);

    float bp = p0, bw = w0; unsigned bc = 0;
    bool risky = false;
    {
        float lhs = p1 * bw, rhs = bp * w1;
        risky |= fabsf(lhs - rhs) <= 2e-6f + 2e-6f * (lhs + rhs);
        if (lhs > rhs) { bp = p1; bw = w1; bc = 1; }
    }
    {
        float lhs = p2 * bw, rhs = bp * w2;
        risky |= fabsf(lhs - rhs) <= 2e-6f + 2e-6f * (lhs + rhs);
        if (lhs > rhs) { bp = p2; bw = w2; bc = 2; }
    }
    {
        float lhs = p3 * bw, rhs = bp * w3;
        risky |= fabsf(lhs - rhs) <= 2e-6f + 2e-6f * (lhs + rhs);
        if (lhs > rhs) { bp = p3; bw = w3; bc = 3; }
    }
    if (risky) {           // rare: redo with precise log2f
        w0 = -log2f(u0);
        w1 = -log2f(u1);
        w2 = -log2f(u2);
        w3 = -log2f(u3);
        bp = p0; bw = w0; bc = 0;
        if (p1 * bw > bp * w1) { bp = p1; bw = w1; bc = 1; }
        if (p2 * bw > bp * w2) { bp = p2; bw = w2; bc = 2; }
        if (p3 * bw > bp * w3) { bp = p3; bw = w3; bc = 3; }
    }
    g_cls[gid] = (uint8_t)bc;
}

// ---------------------------------------------------------------------------
// K2: per task t (40) and 16-row block (32): 5x5 box counts of each class,
//     packed one class per byte lane of a u32 (counts <= 25). Horizontal sum
//     via per-thread sliding window over padded smem. For each fg pixel,
//     key = (count<<18) | (0x3FFFF - flat_idx); atomicMax -> max count,
//     lowest flat index on ties. (Bit-identical to rounds 1-3.)
// ---------------------------------------------------------------------------
__global__ void __launch_bounds__(256) k_seed() {
    __shared__ uint32_t           scls[20][129];   // class bytes (+pad)
    __shared__ uint32_t           svsP[16][517];   // vert 5-sums; col idx x+2
    __shared__ unsigned long long sbest[3];

    int tid = threadIdx.x;
    int t   = blockIdx.y;
    int r0  = blockIdx.x * 16;
    const uint32_t* cls32 = (const uint32_t*)g_cls + (size_t)t * (NPIX/4);

    for (int i = tid; i < 20 * 128; i += 256) {
        int row = i >> 7, wd = i & 127;
        int rr = r0 - 2 + row;
        scls[row][wd] = (rr >= 0 && rr < HH) ? cls32[rr * 128 + wd] : 0u;
    }
    if (tid < 3) sbest[tid] = 0ull;
    if (tid < 64) {                    // zero border columns 0,1,514,515
        int y = tid >> 2, b = tid & 3;
        int col = (b < 2) ? b : 512 + b;
        svsP[y][col] = 0u;
    }
    __syncthreads();

    // vertical sliding 5-sums (packed per-class byte lanes)
    for (int x = tid; x < 512; x += 256) {
        int wd = x >> 2, sh = (x & 3) * 8;
        uint32_t w = 0;
#pragma unroll
        for (int k = 0; k < 5; k++) {
            uint32_t b = (scls[k][wd] >> sh) & 0xFFu;
            w += 1u << (b << 3);
        }
        svsP[0][x + 2] = w;
        for (int y = 1; y < 16; y++) {
            uint32_t ba = (scls[y + 4][wd] >> sh) & 0xFFu;
            uint32_t bs = (scls[y - 1][wd] >> sh) & 0xFFu;
            w += (1u << (ba << 3)) - (1u << (bs << 3));
            svsP[y][x + 2] = w;
        }
    }
    __syncthreads();

    // sliding horizontal window: thread -> (y = tid&15, 32-col chunk)
    unsigned long long lb0 = 0, lb1 = 0, lb2 = 0;
    int y  = tid & 15;
    int xc = (tid >> 4) << 5;
    const uint32_t* sv = svsP[y];
    uint32_t h = sv[xc] + sv[xc+1] + sv[xc+2] + sv[xc+3] + sv[xc+4];
    int wd0 = xc >> 2;
#pragma unroll 1
    for (int w8 = 0; w8 < 8; w8++) {
        uint32_t cw = scls[y + 2][wd0 + w8];
#pragma unroll
        for (int j = 0; j < 4; j++) {
            int x = xc + w8 * 4 + j;
            if (!(w8 == 0 && j == 0)) h += sv[x + 4] - sv[x - 1];
            uint32_t c0 = (cw >> (j * 8)) & 0xFFu;
            if (c0) {
                uint32_t cnt = (h >> (c0 << 3)) & 0xFFu;
                unsigned idx = ((unsigned)(r0 + y) << 9) | (unsigned)x;
                unsigned long long key =
                    ((unsigned long long)cnt << 18) |
                    (unsigned long long)(0x3FFFFu - idx);
                if (c0 == 1u)      { if (key > lb0) lb0 = key; }
                else if (c0 == 2u) { if (key > lb1) lb1 = key; }
                else               { if (key > lb2) lb2 = key; }
            }
        }
    }
    if (lb0) atomicMax(&sbest[0], lb0);
    if (lb1) atomicMax(&sbest[1], lb1);
    if (lb2) atomicMax(&sbest[2], lb2);
    __syncthreads();
    if (tid < 3 && sbest[tid]) atomicMax(&g_seed[t * 3 + tid], sbest[tid]);
}

// ---------------------------------------------------------------------------
// K3: one CTA (128 thr) per (task, class). Bitset flood fill with full
//     horizontal row closure per iteration; 1 barrier/iter via 3-slot flag.
//     Then component log-prob sum over bbox rows; the LAST finishing CTA
//     performs the final loss reduction (fixed tree -> deterministic).
// ---------------------------------------------------------------------------
__device__ __forceinline__ uint32_t word_closure(uint32_t g, uint32_t s) {
    uint32_t up = g & ~(g + s);
    uint32_t gr = __brev(g), sr = __brev(s);
    uint32_t dn = __brev(gr & ~(gr + sr));
    return s | up | dn;
}

__global__ void __launch_bounds__(128) k_flood(const float* __restrict__ preds,
                                               float* __restrict__ out) {
    extern __shared__ uint32_t sm[];
    uint32_t* fg = sm;          // 8192 words
    uint32_t* fl = sm + 8192;   // 8192 words
    __shared__ int s_r0, s_r1;
    __shared__ int s_flag[3];
    __shared__ double s_red[4];
    __shared__ int s_last;

    int tid  = threadIdx.x;
    int task = blockIdx.x;
    int t = task / 3;
    int c = task % 3 + 1;
    int n = t & 3;

    unsigned long long key = g_seed[task];
    double acc = 0.0;
    bool empty = ((key >> 18) == 0ull);

    if (!empty) {
        const uint32_t* cls32 = (const uint32_t*)g_cls + (size_t)t * (NPIX/4);
        uint32_t cpat = (uint32_t)c * 0x01010101u;
        for (int w = tid; w < 8192; w += 128) {
            uint32_t bits = 0;
#pragma unroll
            for (int k = 0; k < 8; k++) {
                uint32_t v  = cls32[w * 8 + k];
                uint32_t eq = __vcmpeq4(v, cpat);
                uint32_t nb = ((eq & 0x01010101u) * 0x01020408u) >> 24;
                bits |= (nb & 0xFu) << (k * 4);
            }
            fg[w] = bits;
            fl[w] = 0u;
        }
        if (tid == 0) {
            int sidx = 0x3FFFF - (int)(key & 0x3FFFFull);
            s_r0 = sidx >> 9; s_r1 = sidx >> 9;
            s_flag[0] = 0; s_flag[1] = 0; s_flag[2] = 0;
        }
        __syncthreads();
        if (tid == 0) {
            int sidx = 0x3FFFF - (int)(key & 0x3FFFFull);
            int sr = sidx >> 9, sc = sidx & 511;
            fl[sr * 16 + (sc >> 5)] = 1u << (sc & 31);
        }
        __syncthreads();

        for (int iter = 0; ; iter++) {
            int p = iter % 3;
            int r0 = s_r0 > 0   ? s_r0 - 1 : 0;
            int r1 = s_r1 < 511 ? s_r1 + 1 : 511;
            int ch = 0, myr0 = 1 << 30, myr1 = -1;
            for (int r = r0 + tid; r <= r1; r += 128) {
                uint32_t* F = fl + r * 16;
                const uint32_t* G = fg + r * 16;
                bool hU = (r > 0), hD = (r < 511);
                const uint32_t* U = fl + (r - 1) * 16;
                const uint32_t* D = fl + (r + 1) * 16;
                uint32_t S[16], Gw[16], Fo[16];
                uint32_t Vp = 0;
                uint32_t Vc = (hU ? U[0] : 0u) | (hD ? D[0] : 0u);
#pragma unroll
                for (int j = 0; j < 16; j++) {
                    uint32_t Vn = (j < 15)
                        ? ((hU ? U[j+1] : 0u) | (hD ? D[j+1] : 0u)) : 0u;
                    Gw[j] = G[j];
                    Fo[j] = F[j];
                    uint32_t vd = Vc | (Vc << 1) | (Vp >> 31) | (Vc >> 1) | (Vn << 31);
                    S[j] = Fo[j] | (vd & Gw[j]);
                    Vp = Vc; Vc = Vn;
                }
                uint32_t carry = 0;
#pragma unroll
                for (int j = 0; j < 16; j++) {
                    uint32_t s = S[j] | (carry & Gw[j] & 1u);
                    uint32_t cl = word_closure(Gw[j], s);
                    S[j] = cl; carry = cl >> 31;
                }
                carry = 0;
                uint32_t diff = 0;
#pragma unroll
                for (int j = 15; j >= 0; j--) {
                    uint32_t s = S[j] | ((0u - carry) & Gw[j] & 0x80000000u);
                    uint32_t cl = word_closure(Gw[j], s);
                    S[j] = cl; carry = cl & 1u;
                    diff |= cl ^ Fo[j];
                }
                if (diff) {
#pragma unroll
                    for (int j = 0; j < 16; j++) F[j] = S[j];
                    ch = 1; if (r < myr0) myr0 = r; if (r > myr1) myr1 = r;
                }
            }
            if (ch) {
                s_flag[p] = 1;
                atomicMin(&s_r0, myr0);
                atomicMax(&s_r1, myr1);
            }
            if (tid == 0) s_flag[(p + 1) % 3] = 0;
            __syncthreads();
            if (!s_flag[p]) break;
        }

        const float* pb = preds + ((size_t)(n * 4 + c) << 18);
        int w0 = s_r0 * 16, w1 = (s_r1 + 1) * 16;
        for (int w = w0 + tid; w < w1; w += 128) {
            uint32_t m = fl[w];
            int rowbase = (w >> 4) << 9;
            int colbase = (w & 15) << 5;
            while (m) {
                int b = __ffs(m) - 1;
                m &= m - 1;
                float p = pb[rowbase + colbase + b];
                acc += (double)logf(p + 1e-16f);
            }
        }
    }

#pragma unroll
    for (int off = 16; off; off >>= 1)
        acc += __shfl_down_sync(0xFFFFFFFFu, acc, off);
    if ((tid & 31) == 0) s_red[tid >> 5] = acc;
    __syncthreads();
    if (tid == 0) {
        double tt = s_red[0] + s_red[1] + s_red[2] + s_red[3];
        g_partial[task] = tt;
        __threadfence();
        int old = atomicAdd(&g_done, 1);
        s_last = (old == NTASK * 3 - 1);
    }
    __syncthreads();

    if (s_last) {
        __threadfence();
        double v = (tid < NTASK * 3) ? g_partial[tid] : 0.0;
#pragma unroll
        for (int off = 16; off; off >>= 1)
            v += __shfl_down_sync(0xFFFFFFFFu, v, off);
        if ((tid & 31) == 0) s_red[tid >> 5] = v;
        __syncthreads();
        if (tid == 0) {
            double s = s_red[0] + s_red[1] + s_red[2] + s_red[3];
            out[0] = (float)(-s / (double)TOTPIX);
        }
    }
}

// ---------------------------------------------------------------------------
extern "C" void kernel_launch(void* const* d_in, const int* in_sizes, int n_in,
                              void* d_out, int out_size) {
    (void)in_sizes; (void)n_in; (void)out_size;
    const float* preds = (const float*)d_in[0];
    float* out = (float*)d_out;

    cudaFuncSetAttribute(k_flood, cudaFuncAttributeMaxDynamicSharedMemorySize,
                         2 * 8192 * (int)sizeof(uint32_t));

    k_sample<<<(TOTPIX + 255) / 256, 256>>>(preds);
    {
        dim3 g(HH / 16, NTASK);
        k_seed<<<g, 256>>>();
    }
    k_flood<<<NTASK * 3, 128, 2 * 8192 * sizeof(uint32_t)>>>(preds, out);
}

// round 5
// speedup vs baseline: 1.1806x; 1.1806x over previous
#include <cuda_runtime.h>
#include <cstdint>

// ===========================================================================
// reinforce_cons_loss:
//   K1 Threefry-2x32 Gumbel-max sampling (funnelshift rounds — round-3 form;
//      IMAD.WIDE rotate was a verified regression in round 4)
//   K2 5x5 fg-neighbor counts + per-(task,class) argmax seed (sliding window)
//   K3 per-(task,class) 8-connectivity flood fill (bitset row closure)
//      + component log-prob sum + last-CTA final loss reduction
// ===========================================================================

#define NIMG   4
#define NSAMP  10
#define HH     512
#define WW     512
#define NTASK  (NIMG*NSAMP)            // 40 image-samples
#define NPIX   (HH*WW)                 // 262144 = 1<<18
#define TOTPIX ((unsigned)NTASK*NPIX)  // 10485760

__device__ uint8_t            g_cls[(size_t)NTASK * NPIX];
__device__ unsigned long long g_seed[NTASK * 3];
__device__ double             g_partial[NTASK * 3];
__device__ int                g_done;

// ---------------------------------------------------------------------------
// Threefry-2x32, 20 rounds, key (0,42), counter (0, idx); out = x0 ^ x1
// (jax_threefry_partitionable — verified rounds 1-4, rel_err 6e-8)
// ---------------------------------------------------------------------------
#define TF_ROUND(x0,x1,R) { x0 += x1; x1 = __funnelshift_l(x1, x1, (R)); x1 ^= x0; }

__device__ __forceinline__ uint32_t gumbel_bits(uint32_t idx) {
    const uint32_t k0 = 0u, k1 = 42u;
    const uint32_t k2 = k0 ^ k1 ^ 0x1BD11BDAu;
    uint32_t x0 = k0, x1 = idx + k1;
    TF_ROUND(x0,x1,13) TF_ROUND(x0,x1,15) TF_ROUND(x0,x1,26) TF_ROUND(x0,x1,6)
    x0 += k1; x1 += k2 + 1u;
    TF_ROUND(x0,x1,17) TF_ROUND(x0,x1,29) TF_ROUND(x0,x1,16) TF_ROUND(x0,x1,24)
    x0 += k2; x1 += k0 + 2u;
    TF_ROUND(x0,x1,13) TF_ROUND(x0,x1,15) TF_ROUND(x0,x1,26) TF_ROUND(x0,x1,6)
    x0 += k0; x1 += k1 + 3u;
    TF_ROUND(x0,x1,17) TF_ROUND(x0,x1,29) TF_ROUND(x0,x1,16) TF_ROUND(x0,x1,24)
    x0 += k1; x1 += k2 + 4u;
    TF_ROUND(x0,x1,13) TF_ROUND(x0,x1,15) TF_ROUND(x0,x1,26) TF_ROUND(x0,x1,6)
    x0 += k2; x1 += k0 + 5u;
    return x0 ^ x1;
}

// u in (0,1): mantissa from top 23 bits. bits>>9 == umulhi(bits, 2^23) (fma
// pipe), and since bits>>9 < 2^23, OR with 0x3f800000 == ADD (balanceable).
__device__ __forceinline__ float bits_to_u(uint32_t bits) {
    const float tiny = 1.17549435082228751e-38f;
    float f = __uint_as_float(__umulhi(bits, 0x00800000u) + 0x3f800000u) - 1.0f;
    return fmaxf(f, tiny);
}

// ---------------------------------------------------------------------------
// K1: gumbel-max, product form: argmax_c p_c / (-log2 u_c).
//   Fast path = MUFU __log2f; any comparison within a superset threshold of
//   the possible MUFU-induced flip region is redone with precise log2f ->
//   identical argmax to the verified precise path.
// ---------------------------------------------------------------------------
__global__ void __launch_bounds__(256) k_sample(const float* __restrict__ preds) {
    unsigned gid = blockIdx.x * 256u + threadIdx.x;
    if (blockIdx.x == 0) {
        if (threadIdx.x < NTASK * 3) g_seed[threadIdx.x] = 0ull;
        if (threadIdx.x == 0) g_done = 0;
    }
    if (gid >= TOTPIX) return;
    unsigned hw = gid & 0x3FFFFu;
    unsigned n  = (gid >> 18) & 3u;
    const float* pb = preds + ((size_t)n << 20) + hw;   // preds[n][c][h][w]
    unsigned base = gid << 2;

    float p0 = pb[0];
    float p1 = pb[(size_t)1 << 18];
    float p2 = pb[(size_t)2 << 18];
    float p3 = pb[(size_t)3 << 18];

    float u0 = bits_to_u(gumbel_bits(base + 0));
    float u1 = bits_to_u(gumbel_bits(base + 1));
    float u2 = bits_to_u(gumbel_bits(base + 2));
    float u3 = bits_to_u(gumbel_bits(base + 3));

    float w0 = -__log2f(u0);
    float w1 = -__log2f(u1);
    float w2 = -__log2f(u2);
    float w3 = -__log2f(u3);

    float bp = p0, bw = w0; unsigned bc = 0;
    bool risky = false;
    {
        float lhs = p1 * bw, rhs = bp * w1;
        risky |= fabsf(lhs - rhs) <= 2e-6f + 2e-6f * (lhs + rhs);
        if (lhs > rhs) { bp = p1; bw = w1; bc = 1; }
    }
    {
        float lhs = p2 * bw, rhs = bp * w2;
        risky |= fabsf(lhs - rhs) <= 2e-6f + 2e-6f * (lhs + rhs);
        if (lhs > rhs) { bp = p2; bw = w2; bc = 2; }
    }
    {
        float lhs = p3 * bw, rhs = bp * w3;
        risky |= fabsf(lhs - rhs) <= 2e-6f + 2e-6f * (lhs + rhs);
        if (lhs > rhs) { bp = p3; bw = w3; bc = 3; }
    }
    if (risky) {           // rare: redo with precise log2f
        w0 = -log2f(u0);
        w1 = -log2f(u1);
        w2 = -log2f(u2);
        w3 = -log2f(u3);
        bp = p0; bw = w0; bc = 0;
        if (p1 * bw > bp * w1) { bp = p1; bw = w1; bc = 1; }
        if (p2 * bw > bp * w2) { bp = p2; bw = w2; bc = 2; }
        if (p3 * bw > bp * w3) { bp = p3; bw = w3; bc = 3; }
    }
    g_cls[gid] = (uint8_t)bc;
}

// ---------------------------------------------------------------------------
// K2: per task t (40) and 16-row block (32): 5x5 box counts of each class,
//     packed one class per byte lane of a u32 (counts <= 25). Horizontal sum
//     via per-thread sliding window over padded smem. For each fg pixel,
//     key = (count<<18) | (0x3FFFF - flat_idx); atomicMax -> max count,
//     lowest flat index on ties. (Bit-identical to rounds 1-4.)
// ---------------------------------------------------------------------------
__global__ void __launch_bounds__(256) k_seed() {
    __shared__ uint32_t           scls[20][132];   // class bytes (pad->16B align)
    __shared__ uint32_t           svsP[16][517];   // vert 5-sums; col idx x+2
    __shared__ unsigned long long sbest[3];

    int tid = threadIdx.x;
    int t   = blockIdx.y;
    int r0  = blockIdx.x * 16;
    const uint4* cls16 = (const uint4*)((const uint32_t*)g_cls + (size_t)t * (NPIX/4));

    // 20 rows x 32 uint4 loads
    for (int i = tid; i < 20 * 32; i += 256) {
        int row = i >> 5, q = i & 31;
        int rr = r0 - 2 + row;
        uint4 v = (rr >= 0 && rr < HH) ? cls16[rr * 32 + q]
                                       : make_uint4(0u, 0u, 0u, 0u);
        *(uint4*)&scls[row][q * 4] = v;
    }
    if (tid < 3) sbest[tid] = 0ull;
    if (tid < 64) {                    // zero border columns 0,1,514,515
        int y = tid >> 2, b = tid & 3;
        int col = (b < 2) ? b : 512 + b;
        svsP[y][col] = 0u;
    }
    __syncthreads();

    // vertical sliding 5-sums (packed per-class byte lanes)
    for (int x = tid; x < 512; x += 256) {
        int wd = x >> 2, sh = (x & 3) * 8;
        uint32_t w = 0;
#pragma unroll
        for (int k = 0; k < 5; k++) {
            uint32_t b = (scls[k][wd] >> sh) & 0xFFu;
            w += 1u << (b << 3);
        }
        svsP[0][x + 2] = w;
        for (int y = 1; y < 16; y++) {
            uint32_t ba = (scls[y + 4][wd] >> sh) & 0xFFu;
            uint32_t bs = (scls[y - 1][wd] >> sh) & 0xFFu;
            w += (1u << (ba << 3)) - (1u << (bs << 3));
            svsP[y][x + 2] = w;
        }
    }
    __syncthreads();

    // sliding horizontal window: thread -> (y = tid&15, 32-col chunk)
    unsigned long long lb0 = 0, lb1 = 0, lb2 = 0;
    int y  = tid & 15;
    int xc = (tid >> 4) << 5;
    const uint32_t* sv = svsP[y];
    uint32_t h = sv[xc] + sv[xc+1] + sv[xc+2] + sv[xc+3] + sv[xc+4];
    int wd0 = xc >> 2;
#pragma unroll 1
    for (int w8 = 0; w8 < 8; w8++) {
        uint32_t cw = scls[y + 2][wd0 + w8];
#pragma unroll
        for (int j = 0; j < 4; j++) {
            int x = xc + w8 * 4 + j;
            if (!(w8 == 0 && j == 0)) h += sv[x + 4] - sv[x - 1];
            uint32_t c0 = (cw >> (j * 8)) & 0xFFu;
            if (c0) {
                uint32_t cnt = (h >> (c0 << 3)) & 0xFFu;
                unsigned idx = ((unsigned)(r0 + y) << 9) | (unsigned)x;
                unsigned long long key =
                    ((unsigned long long)cnt << 18) |
                    (unsigned long long)(0x3FFFFu - idx);
                if (c0 == 1u)      { if (key > lb0) lb0 = key; }
                else if (c0 == 2u) { if (key > lb1) lb1 = key; }
                else               { if (key > lb2) lb2 = key; }
            }
        }
    }
    if (lb0) atomicMax(&sbest[0], lb0);
    if (lb1) atomicMax(&sbest[1], lb1);
    if (lb2) atomicMax(&sbest[2], lb2);
    __syncthreads();
    if (tid < 3 && sbest[tid]) atomicMax(&g_seed[t * 3 + tid], sbest[tid]);
}

// ---------------------------------------------------------------------------
// K3: one CTA (128 thr) per (task, class). Bitset flood fill with full
//     horizontal row closure per iteration; 1 barrier/iter via 3-slot flag.
//     Then component log-prob sum over bbox rows; the LAST finishing CTA
//     performs the final loss reduction (fixed tree -> deterministic).
// ---------------------------------------------------------------------------
__device__ __forceinline__ uint32_t word_closure(uint32_t g, uint32_t s) {
    uint32_t up = g & ~(g + s);
    uint32_t gr = __brev(g), sr = __brev(s);
    uint32_t dn = __brev(gr & ~(gr + sr));
    return s | up | dn;
}

__device__ __forceinline__ uint32_t nib4(uint32_t v, uint32_t cpat) {
    uint32_t eq = __vcmpeq4(v, cpat);
    return ((eq & 0x01010101u) * 0x01020408u) >> 24;   // 4 bits
}

__global__ void __launch_bounds__(128) k_flood(const float* __restrict__ preds,
                                               float* __restrict__ out) {
    extern __shared__ uint32_t sm[];
    uint32_t* fg = sm;          // 8192 words
    uint32_t* fl = sm + 8192;   // 8192 words
    __shared__ int s_r0, s_r1;
    __shared__ int s_flag[3];
    __shared__ double s_red[4];
    __shared__ int s_last;

    int tid  = threadIdx.x;
    int task = blockIdx.x;
    int t = task / 3;
    int c = task % 3 + 1;
    int n = t & 3;

    unsigned long long key = g_seed[task];
    double acc = 0.0;
    bool empty = ((key >> 18) == 0ull);

    if (!empty) {
        const uint4* cls16 = (const uint4*)((const uint32_t*)g_cls + (size_t)t * (NPIX/4));
        uint32_t cpat = (uint32_t)c * 0x01010101u;
        for (int w = tid; w < 8192; w += 128) {
            uint4 a = cls16[w * 2];
            uint4 b = cls16[w * 2 + 1];
            uint32_t bits =  nib4(a.x, cpat)
                          | (nib4(a.y, cpat) << 4)
                          | (nib4(a.z, cpat) << 8)
                          | (nib4(a.w, cpat) << 12)
                          | (nib4(b.x, cpat) << 16)
                          | (nib4(b.y, cpat) << 20)
                          | (nib4(b.z, cpat) << 24)
                          | (nib4(b.w, cpat) << 28);
            fg[w] = bits;
            fl[w] = 0u;
        }
        if (tid == 0) {
            int sidx = 0x3FFFF - (int)(key & 0x3FFFFull);
            s_r0 = sidx >> 9; s_r1 = sidx >> 9;
            s_flag[0] = 0; s_flag[1] = 0; s_flag[2] = 0;
        }
        __syncthreads();
        if (tid == 0) {
            int sidx = 0x3FFFF - (int)(key & 0x3FFFFull);
            int sr = sidx >> 9, sc = sidx & 511;
            fl[sr * 16 + (sc >> 5)] = 1u << (sc & 31);
        }
        __syncthreads();

        for (int iter = 0; ; iter++) {
            int p = iter % 3;
            int r0 = s_r0 > 0   ? s_r0 - 1 : 0;
            int r1 = s_r1 < 511 ? s_r1 + 1 : 511;
            int ch = 0, myr0 = 1 << 30, myr1 = -1;
            for (int r = r0 + tid; r <= r1; r += 128) {
                uint32_t* F = fl + r * 16;
                const uint32_t* G = fg + r * 16;
                bool hU = (r > 0), hD = (r < 511);
                const uint32_t* U = fl + (r - 1) * 16;
                const uint32_t* D = fl + (r + 1) * 16;
                uint32_t S[16], Gw[16], Fo[16];
                uint32_t Vp = 0;
                uint32_t Vc = (hU ? U[0] : 0u) | (hD ? D[0] : 0u);
#pragma unroll
                for (int j = 0; j < 16; j++) {
                    uint32_t Vn = (j < 15)
                        ? ((hU ? U[j+1] : 0u) | (hD ? D[j+1] : 0u)) : 0u;
                    Gw[j] = G[j];
                    Fo[j] = F[j];
                    uint32_t vd = Vc | (Vc << 1) | (Vp >> 31) | (Vc >> 1) | (Vn << 31);
                    S[j] = Fo[j] | (vd & Gw[j]);
                    Vp = Vc; Vc = Vn;
                }
                uint32_t carry = 0;
#pragma unroll
                for (int j = 0; j < 16; j++) {
                    uint32_t s = S[j] | (carry & Gw[j] & 1u);
                    uint32_t cl = word_closure(Gw[j], s);
                    S[j] = cl; carry = cl >> 31;
                }
                carry = 0;
                uint32_t diff = 0;
#pragma unroll
                for (int j = 15; j >= 0; j--) {
                    uint32_t s = S[j] | ((0u - carry) & Gw[j] & 0x80000000u);
                    uint32_t cl = word_closure(Gw[j], s);
                    S[j] = cl; carry = cl & 1u;
                    diff |= cl ^ Fo[j];
                }
                if (diff) {
#pragma unroll
                    for (int j = 0; j < 16; j++) F[j] = S[j];
                    ch = 1; if (r < myr0) myr0 = r; if (r > myr1) myr1 = r;
                }
            }
            if (ch) {
                s_flag[p] = 1;
                atomicMin(&s_r0, myr0);
                atomicMax(&s_r1, myr1);
            }
            if (tid == 0) s_flag[(p + 1) % 3] = 0;
            __syncthreads();
            if (!s_flag[p]) break;
        }

        const float* pb = preds + ((size_t)(n * 4 + c) << 18);
        int w0 = s_r0 * 16, w1 = (s_r1 + 1) * 16;
        for (int w = w0 + tid; w < w1; w += 128) {
            uint32_t m = fl[w];
            int rowbase = (w >> 4) << 9;
            int colbase = (w & 15) << 5;
            while (m) {
                int b = __ffs(m) - 1;
                m &= m - 1;
                float p = pb[rowbase + colbase + b];
                acc += (double)logf(p + 1e-16f);
            }
        }
    }

#pragma unroll
    for (int off = 16; off; off >>= 1)
        acc += __shfl_down_sync(0xFFFFFFFFu, acc, off);
    if ((tid & 31) == 0) s_red[tid >> 5] = acc;
    __syncthreads();
    if (tid == 0) {
        double tt = s_red[0] + s_red[1] + s_red[2] + s_red[3];
        g_partial[task] = tt;
        __threadfence();
        int old = atomicAdd(&g_done, 1);
        s_last = (old == NTASK * 3 - 1);
    }
    __syncthreads();

    if (s_last) {
        __threadfence();
        double v = (tid < NTASK * 3) ? g_partial[tid] : 0.0;
#pragma unroll
        for (int off = 16; off; off >>= 1)
            v += __shfl_down_sync(0xFFFFFFFFu, v, off);
        if ((tid & 31) == 0) s_red[tid >> 5] = v;
        __syncthreads();
        if (tid == 0) {
            double s = s_red[0] + s_red[1] + s_red[2] + s_red[3];
            out[0] = (float)(-s / (double)TOTPIX);
        }
    }
}

// ---------------------------------------------------------------------------
extern "C" void kernel_launch(void* const* d_in, const int* in_sizes, int n_in,
                              void* d_out, int out_size) {
    (void)in_sizes; (void)n_in; (void)out_size;
    const float* preds = (const float*)d_in[0];
    float* out = (float*)d_out;

    cudaFuncSetAttribute(k_flood, cudaFuncAttributeMaxDynamicSharedMemorySize,
                         2 * 8192 * (int)sizeof(uint32_t));

    k_sample<<<(TOTPIX + 255) / 256, 256>>>(preds);
    {
        dim3 g(HH / 16, NTASK);
        k_seed<<<g, 256>>>();
    }
    k_flood<<<NTASK * 3, 128, 2 * 8192 * sizeof(uint32_t)>>>(preds, out);
}